// round 1
// baseline (speedup 1.0000x reference)
#include <cuda_runtime.h>

#define BDIM  1024
#define HEADS 16
#define HD    64
#define LSEQ  1024
#define BATCH 8
#define MROWS (BATCH * LSEQ)   // 8192

// Scratch (allocation-free rule: __device__ globals)
__device__ float g_Q[BATCH * HEADS * LSEQ * HD];  // (B,H,L,hd)
__device__ float g_K[BATCH * HEADS * LSEQ * HD];
__device__ float g_V[BATCH * HEADS * LSEQ * HD];
__device__ float g_Y[BATCH * LSEQ * BDIM];        // (B,L,D)

// ---------------------------------------------------------------------------
// Tiled GEMM: C[m][n] = sum_k A[m][k] * W[n][k] + bias[n]
// A: (M=8192, K=1024) row-major, W: (N=1024, K=1024) row-major.
// Block tile 64x64, K-tile 16, 256 threads, 4x4 per thread.
// HEADS_OUT: scatter output to (B,H,L,hd) layout; else plain (M,N).
// ---------------------------------------------------------------------------
template <bool HEADS_OUT>
__global__ __launch_bounds__(256) void gemm64(const float* __restrict__ A,
                                              const float* __restrict__ W,
                                              const float* __restrict__ bias,
                                              float* __restrict__ C) {
    __shared__ float As[16][68];  // As[k][m]
    __shared__ float Bs[16][68];  // Bs[k][n]

    const int tx = threadIdx.x & 15;
    const int ty = threadIdx.x >> 4;
    const int m0 = blockIdx.y * 64;
    const int n0 = blockIdx.x * 64;

    const int lrow = threadIdx.x >> 2;  // 0..63
    const int lc4  = threadIdx.x & 3;   // 0..3

    const float* Aptr = A + (m0 + lrow) * BDIM + lc4 * 4;
    const float* Wptr = W + (n0 + lrow) * BDIM + lc4 * 4;

    float acc[4][4] = {};

    for (int k0 = 0; k0 < BDIM; k0 += 16) {
        float4 av = *(const float4*)(Aptr + k0);
        float4 wv = *(const float4*)(Wptr + k0);
        __syncthreads();  // protect previous-tile smem reads
        As[lc4 * 4 + 0][lrow] = av.x;
        As[lc4 * 4 + 1][lrow] = av.y;
        As[lc4 * 4 + 2][lrow] = av.z;
        As[lc4 * 4 + 3][lrow] = av.w;
        Bs[lc4 * 4 + 0][lrow] = wv.x;
        Bs[lc4 * 4 + 1][lrow] = wv.y;
        Bs[lc4 * 4 + 2][lrow] = wv.z;
        Bs[lc4 * 4 + 3][lrow] = wv.w;
        __syncthreads();
#pragma unroll
        for (int kk = 0; kk < 16; kk++) {
            float4 a = *(const float4*)&As[kk][ty * 4];
            float4 b = *(const float4*)&Bs[kk][tx * 4];
            float af[4] = {a.x, a.y, a.z, a.w};
            float bf[4] = {b.x, b.y, b.z, b.w};
#pragma unroll
            for (int i = 0; i < 4; i++)
#pragma unroll
                for (int j = 0; j < 4; j++) acc[i][j] = fmaf(af[i], bf[j], acc[i][j]);
        }
    }

    const int nb = n0 + tx * 4;
    const float4 bvec = *(const float4*)(bias + nb);
    const float bb[4] = {bvec.x, bvec.y, bvec.z, bvec.w};

#pragma unroll
    for (int i = 0; i < 4; i++) {
        const int m = m0 + ty * 4 + i;
        float4 out;
        out.x = acc[i][0] + bb[0];
        out.y = acc[i][1] + bb[1];
        out.z = acc[i][2] + bb[2];
        out.w = acc[i][3] + bb[3];
        if (HEADS_OUT) {
            const int b = m >> 10;       // m / LSEQ
            const int l = m & 1023;
            const int h = nb >> 6;
            const int c = nb & 63;
            *(float4*)(C + (((b * HEADS + h) * LSEQ) + l) * HD + c) = out;
        } else {
            *(float4*)(C + m * BDIM + nb) = out;
        }
    }
}

// ---------------------------------------------------------------------------
// Flash-attention block: Br=Bc=64, hd=64, causal, fp32, online softmax.
// Grid: (L/64, B*H). 256 threads, 4x4 output per thread.
// Dynamic smem: Qt[64][68] (Qt[d][r]) + Kt[64][68] (Kt[d][c]) +
//               Vs[64][68] (Vs[k][c]) + Ps[64][68] + m/l/scale[64 each]
// ---------------------------------------------------------------------------
__global__ __launch_bounds__(256) void attn64(const float* __restrict__ Q,
                                              const float* __restrict__ K,
                                              const float* __restrict__ V,
                                              float* __restrict__ Y) {
    extern __shared__ float sm[];
    float* Qt  = sm;               // 64*68
    float* Kt  = Qt + 64 * 68;
    float* Vs  = Kt + 64 * 68;
    float* Ps  = Vs + 64 * 68;
    float* m_s = Ps + 64 * 68;     // 64
    float* l_s = m_s + 64;
    float* c_s = l_s + 64;

    const int tid = threadIdx.x;
    const int tx = tid & 15;
    const int ty = tid >> 4;
    const int qt = blockIdx.x;
    const int bh = blockIdx.y;

    const float* Qb = Q + bh * LSEQ * HD;
    const float* Kb = K + bh * LSEQ * HD;
    const float* Vb = V + bh * LSEQ * HD;

    // Load Q tile transposed: Qt[d][r]
#pragma unroll
    for (int i = 0; i < 4; i++) {
        const int f = tid + i * 256;          // 0..1023 float4 id
        const int r = f >> 4;
        const int c4 = f & 15;
        float4 v = *(const float4*)(Qb + (qt * 64 + r) * HD + c4 * 4);
        Qt[(c4 * 4 + 0) * 68 + r] = v.x;
        Qt[(c4 * 4 + 1) * 68 + r] = v.y;
        Qt[(c4 * 4 + 2) * 68 + r] = v.z;
        Qt[(c4 * 4 + 3) * 68 + r] = v.w;
    }
    if (tid < 64) { m_s[tid] = -1e30f; l_s[tid] = 0.0f; }

    float acc[4][4] = {};

    for (int kt = 0; kt <= qt; kt++) {
        __syncthreads();  // protect prior-tile reads (and publish Qt/m_s on first iter)
        // Load K tile transposed (Kt[d][c]) and V tile row-major (Vs[k][c])
#pragma unroll
        for (int i = 0; i < 4; i++) {
            const int f = tid + i * 256;
            const int r = f >> 4;
            const int c4 = f & 15;
            float4 kv = *(const float4*)(Kb + (kt * 64 + r) * HD + c4 * 4);
            Kt[(c4 * 4 + 0) * 68 + r] = kv.x;
            Kt[(c4 * 4 + 1) * 68 + r] = kv.y;
            Kt[(c4 * 4 + 2) * 68 + r] = kv.z;
            Kt[(c4 * 4 + 3) * 68 + r] = kv.w;
            float4 vv = *(const float4*)(Vb + (kt * 64 + r) * HD + c4 * 4);
            *(float4*)&Vs[r * 68 + c4 * 4] = vv;
        }
        __syncthreads();

        // S = Q @ K^T
        float s[4][4] = {};
#pragma unroll
        for (int d = 0; d < 64; d++) {
            float4 a = *(const float4*)&Qt[d * 68 + ty * 4];
            float4 b = *(const float4*)&Kt[d * 68 + tx * 4];
            float af[4] = {a.x, a.y, a.z, a.w};
            float bf[4] = {b.x, b.y, b.z, b.w};
#pragma unroll
            for (int i = 0; i < 4; i++)
#pragma unroll
                for (int j = 0; j < 4; j++) s[i][j] = fmaf(af[i], bf[j], s[i][j]);
        }
        // scale + causal mask, stage to smem
#pragma unroll
        for (int i = 0; i < 4; i++) {
            const int gr = qt * 64 + ty * 4 + i;
#pragma unroll
            for (int j = 0; j < 4; j++) {
                const int gc = kt * 64 + tx * 4 + j;
                float v = s[i][j] * 0.125f;  // 1/sqrt(64)
                if (gc > gr) v = -1e30f;
                Ps[(ty * 4 + i) * 68 + (tx * 4 + j)] = v;
            }
        }
        __syncthreads();

        // Online softmax: 4 threads per row, 16 cols each (lanes r*4..r*4+3)
        {
            const int r = tid >> 2;
            const int sub = tid & 3;
            float* row = &Ps[r * 68 + sub * 16];
            float mx = -1e30f;
#pragma unroll
            for (int c = 0; c < 16; c++) mx = fmaxf(mx, row[c]);
            mx = fmaxf(mx, __shfl_xor_sync(0xffffffffu, mx, 1));
            mx = fmaxf(mx, __shfl_xor_sync(0xffffffffu, mx, 2));
            const float m_old = m_s[r];
            const float m_new = fmaxf(m_old, mx);
            float sum = 0.0f;
#pragma unroll
            for (int c = 0; c < 16; c++) {
                float p = __expf(row[c] - m_new);
                row[c] = p;
                sum += p;
            }
            sum += __shfl_xor_sync(0xffffffffu, sum, 1);
            sum += __shfl_xor_sync(0xffffffffu, sum, 2);
            if (sub == 0) {
                const float corr = __expf(m_old - m_new);
                l_s[r] = l_s[r] * corr + sum;
                m_s[r] = m_new;
                c_s[r] = corr;
            }
        }
        __syncthreads();

        // Rescale accumulators, then O += P @ V
        float corr[4];
#pragma unroll
        for (int i = 0; i < 4; i++) corr[i] = c_s[ty * 4 + i];
#pragma unroll
        for (int i = 0; i < 4; i++)
#pragma unroll
            for (int j = 0; j < 4; j++) acc[i][j] *= corr[i];

#pragma unroll
        for (int kk = 0; kk < 64; kk++) {
            float4 b = *(const float4*)&Vs[kk * 68 + tx * 4];
            float bf[4] = {b.x, b.y, b.z, b.w};
            float af[4];
#pragma unroll
            for (int i = 0; i < 4; i++) af[i] = Ps[(ty * 4 + i) * 68 + kk];
#pragma unroll
            for (int i = 0; i < 4; i++)
#pragma unroll
                for (int j = 0; j < 4; j++) acc[i][j] = fmaf(af[i], bf[j], acc[i][j]);
        }
    }

    // Normalize and write to (B,L,D) layout
    const int b = bh >> 4;
    const int h = bh & 15;
#pragma unroll
    for (int i = 0; i < 4; i++) {
        const int r = ty * 4 + i;
        const float inv = 1.0f / l_s[r];
        const int l = qt * 64 + r;
        float4 out;
        out.x = acc[i][0] * inv;
        out.y = acc[i][1] * inv;
        out.z = acc[i][2] * inv;
        out.w = acc[i][3] * inv;
        *(float4*)(Y + ((size_t)(b * LSEQ + l)) * BDIM + h * HD + tx * 4) = out;
    }
}

// ---------------------------------------------------------------------------
extern "C" void kernel_launch(void* const* d_in, const int* in_sizes, int n_in,
                              void* d_out, int out_size) {
    const float* key   = (const float*)d_in[0];
    const float* value = (const float*)d_in[1];
    const float* query = (const float*)d_in[2];
    const float* Wk    = (const float*)d_in[3];
    const float* bk    = (const float*)d_in[4];
    const float* Wq    = (const float*)d_in[5];
    const float* bq    = (const float*)d_in[6];
    const float* Wv    = (const float*)d_in[7];
    const float* bv    = (const float*)d_in[8];
    const float* Wp    = (const float*)d_in[9];
    const float* bp    = (const float*)d_in[10];
    float* out = (float*)d_out;

    float *Qd, *Kd, *Vd, *Yd;
    cudaGetSymbolAddress((void**)&Qd, g_Q);
    cudaGetSymbolAddress((void**)&Kd, g_K);
    cudaGetSymbolAddress((void**)&Vd, g_V);
    cudaGetSymbolAddress((void**)&Yd, g_Y);

    dim3 gridP(BDIM / 64, MROWS / 64);  // (16, 128)
    gemm64<true><<<gridP, 256>>>(query, Wq, bq, Qd);
    gemm64<true><<<gridP, 256>>>(key,   Wk, bk, Kd);
    gemm64<true><<<gridP, 256>>>(value, Wv, bv, Vd);

    const int attn_smem = (4 * 64 * 68 + 3 * 64) * (int)sizeof(float);  // ~70.4 KB
    static bool attr_set = false;
    cudaFuncSetAttribute(attn64, cudaFuncAttributeMaxDynamicSharedMemorySize, attn_smem);
    (void)attr_set;
    dim3 gridA(LSEQ / 64, BATCH * HEADS);  // (16, 128)
    attn64<<<gridA, 256, attn_smem>>>(Qd, Kd, Vd, Yd);

    gemm64<false><<<gridP, 256>>>(Yd, Wp, bp, out);
}

// round 3
// speedup vs baseline: 1.8432x; 1.8432x over previous
#include <cuda_runtime.h>
#include <cuda_bf16.h>
#include <cstdint>

#define BDIM  1024
#define HEADS 16
#define HD    64
#define LSEQ  1024
#define BATCH 8
#define MROWS (BATCH * LSEQ)   // 8192

// ---------------------------------------------------------------------------
// Scratch (__device__ globals; allocation-free rule)
// ---------------------------------------------------------------------------
__device__ float g_Q[BATCH * HEADS * LSEQ * HD];
__device__ float g_K[BATCH * HEADS * LSEQ * HD];
__device__ float g_V[BATCH * HEADS * LSEQ * HD];
__device__ float g_Y[MROWS * BDIM];
__device__ __nv_bfloat16 g_ahi[MROWS * BDIM];
__device__ __nv_bfloat16 g_alo[MROWS * BDIM];
__device__ __nv_bfloat16 g_whi[BDIM * BDIM];
__device__ __nv_bfloat16 g_wlo[BDIM * BDIM];

// ---------------------------------------------------------------------------
// PTX helpers (base-target only: ldmatrix / mma.sync / cp.async)
// ---------------------------------------------------------------------------
__device__ __forceinline__ uint32_t smem_u32(const void* p) {
    uint32_t a;
    asm("{ .reg .u64 t; cvta.to.shared.u64 t, %1; cvt.u32.u64 %0, t; }" : "=r"(a) : "l"(p));
    return a;
}
__device__ __forceinline__ void ldmx4(uint32_t r[4], uint32_t a) {
    asm volatile("ldmatrix.sync.aligned.m8n8.x4.shared.b16 {%0,%1,%2,%3}, [%4];"
                 : "=r"(r[0]), "=r"(r[1]), "=r"(r[2]), "=r"(r[3]) : "r"(a));
}
__device__ __forceinline__ void mma_bf16(float c[4], const uint32_t a[4],
                                         uint32_t b0, uint32_t b1) {
    asm volatile(
        "mma.sync.aligned.m16n8k16.row.col.f32.bf16.bf16.f32 "
        "{%0,%1,%2,%3}, {%4,%5,%6,%7}, {%8,%9}, {%0,%1,%2,%3};"
        : "+f"(c[0]), "+f"(c[1]), "+f"(c[2]), "+f"(c[3])
        : "r"(a[0]), "r"(a[1]), "r"(a[2]), "r"(a[3]), "r"(b0), "r"(b1));
}
__device__ __forceinline__ void cp16(uint32_t s, const void* g) {
    asm volatile("cp.async.cg.shared.global [%0], [%1], 16;" :: "r"(s), "l"(g));
}

// ---------------------------------------------------------------------------
// fp32 -> (hi, lo) bf16 split
// ---------------------------------------------------------------------------
struct __align__(8) BF4 { __nv_bfloat16 v[4]; };

__global__ __launch_bounds__(256) void convert_hilo(const float* __restrict__ src,
                                                    __nv_bfloat16* __restrict__ hi,
                                                    __nv_bfloat16* __restrict__ lo,
                                                    int n4) {
    int i = blockIdx.x * blockDim.x + threadIdx.x;
    if (i >= n4) return;
    float4 v = reinterpret_cast<const float4*>(src)[i];
    float f[4] = {v.x, v.y, v.z, v.w};
    BF4 h, l;
#pragma unroll
    for (int j = 0; j < 4; j++) {
        __nv_bfloat16 hb = __float2bfloat16(f[j]);
        h.v[j] = hb;
        l.v[j] = __float2bfloat16(f[j] - __bfloat162float(hb));
    }
    reinterpret_cast<BF4*>(hi)[i] = h;
    reinterpret_cast<BF4*>(lo)[i] = l;
}

// ---------------------------------------------------------------------------
// HMMA GEMM: C[m][n] = sum_k A[m][k]*W[n][k] + bias[n]
// A (8192 x 1024), W (1024 x 1024), both as hi/lo bf16 pairs (K-major).
// CTA tile 128x128, K-chunk 32, cp.async double buffer, 8 warps (64x32 each).
// D = Ahi*Whi + Ahi*Wlo + Alo*Whi accumulated in fp32.
// smem tile: 128 rows x 32 bf16, pitch 40 bf16 (80B) -> conflict-free ldmatrix.
// ---------------------------------------------------------------------------
#define TPITCH     40                    // bf16 elements per row (80 bytes)
#define TILE_B     (128 * TPITCH * 2)    // 10240 bytes per tile
#define BUF_B      (4 * TILE_B)          // Ahi,Alo,Whi,Wlo = 40960
#define GEMM_SMEM  (2 * BUF_B)           // 81920

template <bool HEADS_OUT>
__global__ __launch_bounds__(256) void gemm_mma(const __nv_bfloat16* __restrict__ Ahi,
                                                const __nv_bfloat16* __restrict__ Alo,
                                                const __nv_bfloat16* __restrict__ Whi,
                                                const __nv_bfloat16* __restrict__ Wlo,
                                                const float* __restrict__ bias,
                                                float* __restrict__ C) {
    extern __shared__ char smem[];
    const uint32_t sbase = smem_u32(smem);
    const int tid = threadIdx.x;
    const int wid = tid >> 5;
    const int lane = tid & 31;
    const int m0 = blockIdx.y * 128;
    const int n0 = blockIdx.x * 128;

    const __nv_bfloat16* srcs[4] = {Ahi + (size_t)m0 * BDIM, Alo + (size_t)m0 * BDIM,
                                    Whi + (size_t)n0 * BDIM, Wlo + (size_t)n0 * BDIM};

    // cp.async: 4 tiles x 128 rows x 4 segs(16B) = 2048 transfers, 8 per thread
    auto issue = [&](int c) {
        const int koff = c * 32;
        const uint32_t dbase = sbase + (c & 1) * BUF_B;
#pragma unroll
        for (int t = 0; t < 8; t++) {
            const int gid = t * 256 + tid;
            const int tile = gid >> 9;
            const int id = gid & 511;
            const int row = id >> 2;
            const int seg = id & 3;
            cp16(dbase + tile * TILE_B + row * 80 + seg * 16,
                 srcs[tile] + row * BDIM + koff + seg * 8);
        }
        asm volatile("cp.async.commit_group;");
    };

    const int warp_m = (wid >> 2) * 64;   // 0 or 64
    const int warp_n = (wid & 3) * 32;    // 0,32,64,96

    // ldmatrix address components
    const int a_row = warp_m + (lane & 15);        // + mf*16
    const int a_k8  = (lane >> 4) * 8;             // + ks*16
    const int b_row = warp_n + (lane & 7) + ((lane >> 4) << 3);  // + nf2*16
    const int b_k8  = ((lane >> 3) & 1) * 8;

    float acc[4][4][4] = {};

    issue(0);
    for (int c = 0; c < 32; c++) {
        if (c + 1 < 32) {
            issue(c + 1);
            asm volatile("cp.async.wait_group 1;" ::: "memory");
        } else {
            asm volatile("cp.async.wait_group 0;" ::: "memory");
        }
        __syncthreads();
        const uint32_t bb = sbase + (c & 1) * BUF_B;
        const uint32_t aHiB = bb;
        const uint32_t aLoB = bb + TILE_B;
        const uint32_t wHiB = bb + 2 * TILE_B;
        const uint32_t wLoB = bb + 3 * TILE_B;
#pragma unroll
        for (int ks = 0; ks < 2; ks++) {
            const int kc = ks * 16;
            uint32_t ra[4][4];
#pragma unroll
            for (int mf = 0; mf < 4; mf++)
                ldmx4(ra[mf], aHiB + (a_row + mf * 16) * 80 + (kc + a_k8) * 2);
            uint32_t rbh[2][4], rbl[2][4];
#pragma unroll
            for (int nf2 = 0; nf2 < 2; nf2++) {
                const uint32_t off = (b_row + nf2 * 16) * 80 + (kc + b_k8) * 2;
                ldmx4(rbh[nf2], wHiB + off);
                ldmx4(rbl[nf2], wLoB + off);
            }
#pragma unroll
            for (int mf = 0; mf < 4; mf++)
#pragma unroll
                for (int nf = 0; nf < 4; nf++) {
                    mma_bf16(acc[mf][nf], ra[mf],
                             rbh[nf >> 1][(nf & 1) * 2], rbh[nf >> 1][(nf & 1) * 2 + 1]);
                    mma_bf16(acc[mf][nf], ra[mf],
                             rbl[nf >> 1][(nf & 1) * 2], rbl[nf >> 1][(nf & 1) * 2 + 1]);
                }
#pragma unroll
            for (int mf = 0; mf < 4; mf++)
                ldmx4(ra[mf], aLoB + (a_row + mf * 16) * 80 + (kc + a_k8) * 2);
#pragma unroll
            for (int mf = 0; mf < 4; mf++)
#pragma unroll
                for (int nf = 0; nf < 4; nf++)
                    mma_bf16(acc[mf][nf], ra[mf],
                             rbh[nf >> 1][(nf & 1) * 2], rbh[nf >> 1][(nf & 1) * 2 + 1]);
        }
        __syncthreads();
    }

    // Epilogue: c0,c1 -> (row g, col 2t..2t+1); c2,c3 -> (row g+8)
#pragma unroll
    for (int mf = 0; mf < 4; mf++) {
        const int mA = m0 + warp_m + mf * 16 + (lane >> 2);
#pragma unroll
        for (int nf = 0; nf < 4; nf++) {
            const int n = n0 + warp_n + nf * 8 + (lane & 3) * 2;
            const float2 bv = *reinterpret_cast<const float2*>(bias + n);
#pragma unroll
            for (int half = 0; half < 2; half++) {
                const int m = mA + half * 8;
                float2 out;
                out.x = acc[mf][nf][half * 2 + 0] + bv.x;
                out.y = acc[mf][nf][half * 2 + 1] + bv.y;
                if (HEADS_OUT) {
                    const int b = m >> 10;
                    const int l = m & 1023;
                    const int h = n >> 6;
                    const int cc = n & 63;
                    *reinterpret_cast<float2*>(C + (((b * HEADS + h) * LSEQ) + l) * HD + cc) = out;
                } else {
                    *reinterpret_cast<float2*>(C + (size_t)m * BDIM + n) = out;
                }
            }
        }
    }
}

// ---------------------------------------------------------------------------
// Flash-attention block (fp32), unchanged
// ---------------------------------------------------------------------------
__global__ __launch_bounds__(256) void attn64(const float* __restrict__ Q,
                                              const float* __restrict__ K,
                                              const float* __restrict__ V,
                                              float* __restrict__ Y) {
    extern __shared__ float sm[];
    float* Qt  = sm;
    float* Kt  = Qt + 64 * 68;
    float* Vs  = Kt + 64 * 68;
    float* Ps  = Vs + 64 * 68;
    float* m_s = Ps + 64 * 68;
    float* l_s = m_s + 64;
    float* c_s = l_s + 64;

    const int tid = threadIdx.x;
    const int tx = tid & 15;
    const int ty = tid >> 4;
    const int qt = blockIdx.x;
    const int bh = blockIdx.y;

    const float* Qb = Q + bh * LSEQ * HD;
    const float* Kb = K + bh * LSEQ * HD;
    const float* Vb = V + bh * LSEQ * HD;

#pragma unroll
    for (int i = 0; i < 4; i++) {
        const int f = tid + i * 256;
        const int r = f >> 4;
        const int c4 = f & 15;
        float4 v = *(const float4*)(Qb + (qt * 64 + r) * HD + c4 * 4);
        Qt[(c4 * 4 + 0) * 68 + r] = v.x;
        Qt[(c4 * 4 + 1) * 68 + r] = v.y;
        Qt[(c4 * 4 + 2) * 68 + r] = v.z;
        Qt[(c4 * 4 + 3) * 68 + r] = v.w;
    }
    if (tid < 64) { m_s[tid] = -1e30f; l_s[tid] = 0.0f; }

    float acc[4][4] = {};

    for (int kt = 0; kt <= qt; kt++) {
        __syncthreads();
#pragma unroll
        for (int i = 0; i < 4; i++) {
            const int f = tid + i * 256;
            const int r = f >> 4;
            const int c4 = f & 15;
            float4 kv = *(const float4*)(Kb + (kt * 64 + r) * HD + c4 * 4);
            Kt[(c4 * 4 + 0) * 68 + r] = kv.x;
            Kt[(c4 * 4 + 1) * 68 + r] = kv.y;
            Kt[(c4 * 4 + 2) * 68 + r] = kv.z;
            Kt[(c4 * 4 + 3) * 68 + r] = kv.w;
            float4 vv = *(const float4*)(Vb + (kt * 64 + r) * HD + c4 * 4);
            *(float4*)&Vs[r * 68 + c4 * 4] = vv;
        }
        __syncthreads();

        float s[4][4] = {};
#pragma unroll
        for (int d = 0; d < 64; d++) {
            float4 a = *(const float4*)&Qt[d * 68 + ty * 4];
            float4 b = *(const float4*)&Kt[d * 68 + tx * 4];
            float af[4] = {a.x, a.y, a.z, a.w};
            float bf[4] = {b.x, b.y, b.z, b.w};
#pragma unroll
            for (int i = 0; i < 4; i++)
#pragma unroll
                for (int j = 0; j < 4; j++) s[i][j] = fmaf(af[i], bf[j], s[i][j]);
        }
#pragma unroll
        for (int i = 0; i < 4; i++) {
            const int gr = qt * 64 + ty * 4 + i;
#pragma unroll
            for (int j = 0; j < 4; j++) {
                const int gc = kt * 64 + tx * 4 + j;
                float v = s[i][j] * 0.125f;
                if (gc > gr) v = -1e30f;
                Ps[(ty * 4 + i) * 68 + (tx * 4 + j)] = v;
            }
        }
        __syncthreads();

        {
            const int r = tid >> 2;
            const int sub = tid & 3;
            float* row = &Ps[r * 68 + sub * 16];
            float mx = -1e30f;
#pragma unroll
            for (int c = 0; c < 16; c++) mx = fmaxf(mx, row[c]);
            mx = fmaxf(mx, __shfl_xor_sync(0xffffffffu, mx, 1));
            mx = fmaxf(mx, __shfl_xor_sync(0xffffffffu, mx, 2));
            const float m_old = m_s[r];
            const float m_new = fmaxf(m_old, mx);
            float sum = 0.0f;
#pragma unroll
            for (int c = 0; c < 16; c++) {
                float p = __expf(row[c] - m_new);
                row[c] = p;
                sum += p;
            }
            sum += __shfl_xor_sync(0xffffffffu, sum, 1);
            sum += __shfl_xor_sync(0xffffffffu, sum, 2);
            if (sub == 0) {
                const float corr = __expf(m_old - m_new);
                l_s[r] = l_s[r] * corr + sum;
                m_s[r] = m_new;
                c_s[r] = corr;
            }
        }
        __syncthreads();

        float corr[4];
#pragma unroll
        for (int i = 0; i < 4; i++) corr[i] = c_s[ty * 4 + i];
#pragma unroll
        for (int i = 0; i < 4; i++)
#pragma unroll
            for (int j = 0; j < 4; j++) acc[i][j] *= corr[i];

#pragma unroll
        for (int kk = 0; kk < 64; kk++) {
            float4 b = *(const float4*)&Vs[kk * 68 + tx * 4];
            float bf[4] = {b.x, b.y, b.z, b.w};
            float af[4];
#pragma unroll
            for (int i = 0; i < 4; i++) af[i] = Ps[(ty * 4 + i) * 68 + kk];
#pragma unroll
            for (int i = 0; i < 4; i++)
#pragma unroll
                for (int j = 0; j < 4; j++) acc[i][j] = fmaf(af[i], bf[j], acc[i][j]);
        }
    }

    const int b = bh >> 4;
    const int h = bh & 15;
#pragma unroll
    for (int i = 0; i < 4; i++) {
        const int r = ty * 4 + i;
        const float inv = 1.0f / l_s[r];
        const int l = qt * 64 + r;
        float4 out;
        out.x = acc[i][0] * inv;
        out.y = acc[i][1] * inv;
        out.z = acc[i][2] * inv;
        out.w = acc[i][3] * inv;
        *(float4*)(Y + ((size_t)(b * LSEQ + l)) * BDIM + h * HD + tx * 4) = out;
    }
}

// ---------------------------------------------------------------------------
extern "C" void kernel_launch(void* const* d_in, const int* in_sizes, int n_in,
                              void* d_out, int out_size) {
    const float* key   = (const float*)d_in[0];
    const float* value = (const float*)d_in[1];
    const float* query = (const float*)d_in[2];
    const float* Wk    = (const float*)d_in[3];
    const float* bk    = (const float*)d_in[4];
    const float* Wq    = (const float*)d_in[5];
    const float* bq    = (const float*)d_in[6];
    const float* Wv    = (const float*)d_in[7];
    const float* bv    = (const float*)d_in[8];
    const float* Wp    = (const float*)d_in[9];
    const float* bp    = (const float*)d_in[10];
    float* out = (float*)d_out;

    float *Qd, *Kd, *Vd, *Yd;
    __nv_bfloat16 *ahi, *alo, *whi, *wlo;
    cudaGetSymbolAddress((void**)&Qd, g_Q);
    cudaGetSymbolAddress((void**)&Kd, g_K);
    cudaGetSymbolAddress((void**)&Vd, g_V);
    cudaGetSymbolAddress((void**)&Yd, g_Y);
    cudaGetSymbolAddress((void**)&ahi, g_ahi);
    cudaGetSymbolAddress((void**)&alo, g_alo);
    cudaGetSymbolAddress((void**)&whi, g_whi);
    cudaGetSymbolAddress((void**)&wlo, g_wlo);

    cudaFuncSetAttribute(gemm_mma<true>,  cudaFuncAttributeMaxDynamicSharedMemorySize, GEMM_SMEM);
    cudaFuncSetAttribute(gemm_mma<false>, cudaFuncAttributeMaxDynamicSharedMemorySize, GEMM_SMEM);

    const int nA4 = MROWS * BDIM / 4;
    const int nW4 = BDIM * BDIM / 4;
    dim3 gG(BDIM / 128, MROWS / 128);   // (8, 64)

    // Q projection
    convert_hilo<<<nA4 / 256, 256>>>(query, ahi, alo, nA4);
    convert_hilo<<<nW4 / 256, 256>>>(Wq, whi, wlo, nW4);
    gemm_mma<true><<<gG, 256, GEMM_SMEM>>>(ahi, alo, whi, wlo, bq, Qd);
    // K projection
    convert_hilo<<<nA4 / 256, 256>>>(key, ahi, alo, nA4);
    convert_hilo<<<nW4 / 256, 256>>>(Wk, whi, wlo, nW4);
    gemm_mma<true><<<gG, 256, GEMM_SMEM>>>(ahi, alo, whi, wlo, bk, Kd);
    // V projection
    convert_hilo<<<nA4 / 256, 256>>>(value, ahi, alo, nA4);
    convert_hilo<<<nW4 / 256, 256>>>(Wv, whi, wlo, nW4);
    gemm_mma<true><<<gG, 256, GEMM_SMEM>>>(ahi, alo, whi, wlo, bv, Vd);

    // Attention (fp32)
    const int attn_smem = (4 * 64 * 68 + 3 * 64) * (int)sizeof(float);
    cudaFuncSetAttribute(attn64, cudaFuncAttributeMaxDynamicSharedMemorySize, attn_smem);
    dim3 gA(LSEQ / 64, BATCH * HEADS);
    attn64<<<gA, 256, attn_smem>>>(Qd, Kd, Vd, Yd);

    // Output projection
    convert_hilo<<<nA4 / 256, 256>>>(Yd, ahi, alo, nA4);
    convert_hilo<<<nW4 / 256, 256>>>(Wp, whi, wlo, nW4);
    gemm_mma<false><<<gG, 256, GEMM_SMEM>>>(ahi, alo, whi, wlo, bp, out);
}

// round 4
// speedup vs baseline: 2.5887x; 1.4045x over previous
#include <cuda_runtime.h>
#include <cuda_bf16.h>
#include <cstdint>

#define BDIM  1024
#define HEADS 16
#define HD    64
#define LSEQ  1024
#define BATCH 8
#define MROWS (BATCH * LSEQ)   // 8192

// ---------------------------------------------------------------------------
// Scratch (__device__ globals; allocation-free rule)
// ---------------------------------------------------------------------------
__device__ __nv_bfloat16 g_qhi[BATCH * HEADS * LSEQ * HD];
__device__ __nv_bfloat16 g_qlo[BATCH * HEADS * LSEQ * HD];
__device__ __nv_bfloat16 g_khi[BATCH * HEADS * LSEQ * HD];
__device__ __nv_bfloat16 g_klo[BATCH * HEADS * LSEQ * HD];
__device__ __nv_bfloat16 g_vhi[BATCH * HEADS * LSEQ * HD];
__device__ __nv_bfloat16 g_vlo[BATCH * HEADS * LSEQ * HD];
__device__ __nv_bfloat16 g_ahi[MROWS * BDIM];
__device__ __nv_bfloat16 g_alo[MROWS * BDIM];
__device__ __nv_bfloat16 g_whi[BDIM * BDIM];
__device__ __nv_bfloat16 g_wlo[BDIM * BDIM];

// ---------------------------------------------------------------------------
// PTX helpers (base-target only)
// ---------------------------------------------------------------------------
__device__ __forceinline__ uint32_t smem_u32(const void* p) {
    uint32_t a;
    asm("{ .reg .u64 t; cvta.to.shared.u64 t, %1; cvt.u32.u64 %0, t; }" : "=r"(a) : "l"(p));
    return a;
}
__device__ __forceinline__ void ldmx4(uint32_t r[4], uint32_t a) {
    asm volatile("ldmatrix.sync.aligned.m8n8.x4.shared.b16 {%0,%1,%2,%3}, [%4];"
                 : "=r"(r[0]), "=r"(r[1]), "=r"(r[2]), "=r"(r[3]) : "r"(a));
}
__device__ __forceinline__ void ldmx4t(uint32_t r[4], uint32_t a) {
    asm volatile("ldmatrix.sync.aligned.m8n8.x4.trans.shared.b16 {%0,%1,%2,%3}, [%4];"
                 : "=r"(r[0]), "=r"(r[1]), "=r"(r[2]), "=r"(r[3]) : "r"(a));
}
__device__ __forceinline__ void mma_bf16(float c[4], const uint32_t a[4],
                                         uint32_t b0, uint32_t b1) {
    asm volatile(
        "mma.sync.aligned.m16n8k16.row.col.f32.bf16.bf16.f32 "
        "{%0,%1,%2,%3}, {%4,%5,%6,%7}, {%8,%9}, {%0,%1,%2,%3};"
        : "+f"(c[0]), "+f"(c[1]), "+f"(c[2]), "+f"(c[3])
        : "r"(a[0]), "r"(a[1]), "r"(a[2]), "r"(a[3]), "r"(b0), "r"(b1));
}
__device__ __forceinline__ void cp16(uint32_t s, const void* g) {
    asm volatile("cp.async.cg.shared.global [%0], [%1], 16;" :: "r"(s), "l"(g));
}
__device__ __forceinline__ void hilo2(float x, float y, uint32_t& hi, uint32_t& lo) {
    __nv_bfloat16 hx = __float2bfloat16(x);
    __nv_bfloat16 hy = __float2bfloat16(y);
    __nv_bfloat162 h = __halves2bfloat162(hx, hy);   // .x = low = even elem
    __nv_bfloat162 l = __halves2bfloat162(
        __float2bfloat16(x - __bfloat162float(hx)),
        __float2bfloat16(y - __bfloat162float(hy)));
    hi = *reinterpret_cast<uint32_t*>(&h);
    lo = *reinterpret_cast<uint32_t*>(&l);
}

// ---------------------------------------------------------------------------
// fp32 -> (hi, lo) bf16 split (for raw inputs & weights)
// ---------------------------------------------------------------------------
struct __align__(8) BF4 { __nv_bfloat16 v[4]; };

__global__ __launch_bounds__(256) void convert_hilo(const float* __restrict__ src,
                                                    __nv_bfloat16* __restrict__ hi,
                                                    __nv_bfloat16* __restrict__ lo,
                                                    int n4) {
    int i = blockIdx.x * blockDim.x + threadIdx.x;
    if (i >= n4) return;
    float4 v = reinterpret_cast<const float4*>(src)[i];
    float f[4] = {v.x, v.y, v.z, v.w};
    BF4 h, l;
#pragma unroll
    for (int j = 0; j < 4; j++) {
        __nv_bfloat16 hb = __float2bfloat16(f[j]);
        h.v[j] = hb;
        l.v[j] = __float2bfloat16(f[j] - __bfloat162float(hb));
    }
    reinterpret_cast<BF4*>(hi)[i] = h;
    reinterpret_cast<BF4*>(lo)[i] = l;
}

// ---------------------------------------------------------------------------
// HMMA GEMM: C[m][n] = sum_k A[m][k]*W[n][k] + bias[n]
// MODE 1: output bf16 hi/lo in (B,H,L,hd) layout.  MODE 0: fp32 (M,N).
// ---------------------------------------------------------------------------
#define TPITCH     40
#define TILE_B     (128 * TPITCH * 2)    // 10240
#define BUF_B      (4 * TILE_B)          // 40960
#define GEMM_SMEM  (2 * BUF_B)           // 81920

template <int MODE>
__global__ __launch_bounds__(256) void gemm_mma(const __nv_bfloat16* __restrict__ Ahi,
                                                const __nv_bfloat16* __restrict__ Alo,
                                                const __nv_bfloat16* __restrict__ Whi,
                                                const __nv_bfloat16* __restrict__ Wlo,
                                                const float* __restrict__ bias,
                                                float* __restrict__ C,
                                                __nv_bfloat16* __restrict__ Chi,
                                                __nv_bfloat16* __restrict__ Clo) {
    extern __shared__ char smem[];
    const uint32_t sbase = smem_u32(smem);
    const int tid = threadIdx.x;
    const int wid = tid >> 5;
    const int lane = tid & 31;
    const int m0 = blockIdx.y * 128;
    const int n0 = blockIdx.x * 128;

    const __nv_bfloat16* srcs[4] = {Ahi + (size_t)m0 * BDIM, Alo + (size_t)m0 * BDIM,
                                    Whi + (size_t)n0 * BDIM, Wlo + (size_t)n0 * BDIM};

    auto issue = [&](int c) {
        const int koff = c * 32;
        const uint32_t dbase = sbase + (c & 1) * BUF_B;
#pragma unroll
        for (int t = 0; t < 8; t++) {
            const int gid = t * 256 + tid;
            const int tile = gid >> 9;
            const int id = gid & 511;
            const int row = id >> 2;
            const int seg = id & 3;
            cp16(dbase + tile * TILE_B + row * 80 + seg * 16,
                 srcs[tile] + row * BDIM + koff + seg * 8);
        }
        asm volatile("cp.async.commit_group;");
    };

    const int warp_m = (wid >> 2) * 64;
    const int warp_n = (wid & 3) * 32;
    const int a_row = warp_m + (lane & 15);
    const int a_k8  = (lane >> 4) * 8;
    const int b_row = warp_n + (lane & 7) + ((lane >> 4) << 3);
    const int b_k8  = ((lane >> 3) & 1) * 8;

    float acc[4][4][4] = {};

    issue(0);
    for (int c = 0; c < 32; c++) {
        if (c + 1 < 32) {
            issue(c + 1);
            asm volatile("cp.async.wait_group 1;" ::: "memory");
        } else {
            asm volatile("cp.async.wait_group 0;" ::: "memory");
        }
        __syncthreads();
        const uint32_t bb = sbase + (c & 1) * BUF_B;
        const uint32_t aHiB = bb;
        const uint32_t aLoB = bb + TILE_B;
        const uint32_t wHiB = bb + 2 * TILE_B;
        const uint32_t wLoB = bb + 3 * TILE_B;
#pragma unroll
        for (int ks = 0; ks < 2; ks++) {
            const int kc = ks * 16;
            uint32_t ra[4][4];
#pragma unroll
            for (int mf = 0; mf < 4; mf++)
                ldmx4(ra[mf], aHiB + (a_row + mf * 16) * 80 + (kc + a_k8) * 2);
            uint32_t rbh[2][4], rbl[2][4];
#pragma unroll
            for (int nf2 = 0; nf2 < 2; nf2++) {
                const uint32_t off = (b_row + nf2 * 16) * 80 + (kc + b_k8) * 2;
                ldmx4(rbh[nf2], wHiB + off);
                ldmx4(rbl[nf2], wLoB + off);
            }
#pragma unroll
            for (int mf = 0; mf < 4; mf++)
#pragma unroll
                for (int nf = 0; nf < 4; nf++) {
                    mma_bf16(acc[mf][nf], ra[mf],
                             rbh[nf >> 1][(nf & 1) * 2], rbh[nf >> 1][(nf & 1) * 2 + 1]);
                    mma_bf16(acc[mf][nf], ra[mf],
                             rbl[nf >> 1][(nf & 1) * 2], rbl[nf >> 1][(nf & 1) * 2 + 1]);
                }
#pragma unroll
            for (int mf = 0; mf < 4; mf++)
                ldmx4(ra[mf], aLoB + (a_row + mf * 16) * 80 + (kc + a_k8) * 2);
#pragma unroll
            for (int mf = 0; mf < 4; mf++)
#pragma unroll
                for (int nf = 0; nf < 4; nf++)
                    mma_bf16(acc[mf][nf], ra[mf],
                             rbh[nf >> 1][(nf & 1) * 2], rbh[nf >> 1][(nf & 1) * 2 + 1]);
        }
        __syncthreads();
    }

#pragma unroll
    for (int mf = 0; mf < 4; mf++) {
        const int mA = m0 + warp_m + mf * 16 + (lane >> 2);
#pragma unroll
        for (int nf = 0; nf < 4; nf++) {
            const int n = n0 + warp_n + nf * 8 + (lane & 3) * 2;
            const float2 bv = *reinterpret_cast<const float2*>(bias + n);
#pragma unroll
            for (int half = 0; half < 2; half++) {
                const int m = mA + half * 8;
                const float ox = acc[mf][nf][half * 2 + 0] + bv.x;
                const float oy = acc[mf][nf][half * 2 + 1] + bv.y;
                if (MODE == 1) {
                    const int b = m >> 10;
                    const int l = m & 1023;
                    const int h = n >> 6;
                    const int cc = n & 63;
                    const size_t idx = (size_t)(((b * HEADS + h) * LSEQ) + l) * HD + cc;
                    uint32_t hi, lo;
                    hilo2(ox, oy, hi, lo);
                    *reinterpret_cast<uint32_t*>(Chi + idx) = hi;
                    *reinterpret_cast<uint32_t*>(Clo + idx) = lo;
                } else {
                    float2 out = {ox, oy};
                    *reinterpret_cast<float2*>(C + (size_t)m * BDIM + n) = out;
                }
            }
        }
    }
}

// ---------------------------------------------------------------------------
// HMMA flash attention: Br=128, Bc=64, hd=64, causal, 3-term hi/lo precision.
// Grid (L/128, B*H), 256 threads (8 warps; warp w owns q rows w*16..w*16+15).
// smem: Q hi/lo (128x64, pitch 144B) + 2-stage K/V hi/lo (64x64 each).
// ---------------------------------------------------------------------------
#define AP 144                          // bytes per smem row (72 bf16)
#define QT_B   (128 * AP)               // 18432 per Q tile
#define KVT_B  (64 * AP)                // 9216 per K/V subtile
#define KVS_B  (4 * KVT_B)              // 36864 per stage
#define ATTN_SMEM (2 * QT_B + 2 * KVS_B)  // 110592

__global__ __launch_bounds__(256) void attn_mma(
    const __nv_bfloat16* __restrict__ qhi, const __nv_bfloat16* __restrict__ qlo,
    const __nv_bfloat16* __restrict__ khi, const __nv_bfloat16* __restrict__ klo,
    const __nv_bfloat16* __restrict__ vhi, const __nv_bfloat16* __restrict__ vlo,
    __nv_bfloat16* __restrict__ yhi, __nv_bfloat16* __restrict__ ylo) {
    extern __shared__ char smem[];
    const uint32_t sb = smem_u32(smem);
    const int tid = threadIdx.x;
    const int wid = tid >> 5;
    const int lane = tid & 31;
    const int qt = blockIdx.x;
    const int bh = blockIdx.y;
    const size_t hoff = (size_t)bh * LSEQ * HD;

    const __nv_bfloat16* qsrc[2] = {qhi + hoff, qlo + hoff};
    const __nv_bfloat16* kvsrc[4] = {khi + hoff, klo + hoff, vhi + hoff, vlo + hoff};

    // Q tiles: 2 x 128 rows x 8 segs = 2048 cp16
#pragma unroll
    for (int t = 0; t < 8; t++) {
        const int gid = t * 256 + tid;
        const int tile = gid >> 10;
        const int id = gid & 1023;
        const int row = id >> 3;
        const int seg = id & 7;
        cp16(sb + tile * QT_B + row * AP + seg * 16,
             qsrc[tile] + (size_t)(qt * 128 + row) * HD + seg * 8);
    }
    auto issue_kv = [&](int kt) {
        const uint32_t dbase = sb + 2 * QT_B + (kt & 1) * KVS_B;
#pragma unroll
        for (int t = 0; t < 8; t++) {
            const int gid = t * 256 + tid;
            const int tile = gid >> 9;
            const int id = gid & 511;
            const int row = id >> 3;
            const int seg = id & 7;
            cp16(dbase + tile * KVT_B + row * AP + seg * 16,
                 kvsrc[tile] + (size_t)(kt * 64 + row) * HD + seg * 8);
        }
        asm volatile("cp.async.commit_group;");
    };
    issue_kv(0);   // group 0 = Q + KV0

    const int a_row = wid * 16 + (lane & 15);
    const int a_k8  = (lane >> 4) * 8;
    const int b_row = (lane & 7) + ((lane >> 4) << 3);
    const int b_k8  = ((lane >> 3) & 1) * 8;
    const int v_row = lane & 15;
    const int v_c8  = (lane >> 4) * 8;

    uint32_t qh[4][4], ql[4][4];
    float oacc[8][4] = {};
    float m0 = -1e30f, m1 = -1e30f, l0 = 0.0f, l1 = 0.0f;

    const int ktmax = 2 * qt + 1;
    for (int kt = 0; kt <= ktmax; kt++) {
        if (kt < ktmax) {
            issue_kv(kt + 1);
            asm volatile("cp.async.wait_group 1;" ::: "memory");
        } else {
            asm volatile("cp.async.wait_group 0;" ::: "memory");
        }
        __syncthreads();
        if (kt == 0) {
#pragma unroll
            for (int ks = 0; ks < 4; ks++) {
                ldmx4(qh[ks], sb + a_row * AP + (ks * 16 + a_k8) * 2);
                ldmx4(ql[ks], sb + QT_B + a_row * AP + (ks * 16 + a_k8) * 2);
            }
        }
        // warp fully above diagonal? (min col > max row)
        const bool skip = (kt * 64) > (qt * 128 + wid * 16 + 15);
        if (!skip) {
            const uint32_t kvb = sb + 2 * QT_B + (kt & 1) * KVS_B;
            const uint32_t kHiB = kvb, kLoB = kvb + KVT_B;
            const uint32_t vHiB = kvb + 2 * KVT_B, vLoB = kvb + 3 * KVT_B;

            // ---- S = Q K^T (3-term) ----
            float sacc[8][4] = {};
#pragma unroll
            for (int ks = 0; ks < 4; ks++) {
#pragma unroll
                for (int nf2 = 0; nf2 < 4; nf2++) {
                    uint32_t bhr[4], blr[4];
                    const uint32_t off = (nf2 * 16 + b_row) * AP + (ks * 16 + b_k8) * 2;
                    ldmx4(bhr, kHiB + off);
                    ldmx4(blr, kLoB + off);
                    mma_bf16(sacc[nf2 * 2],     qh[ks], bhr[0], bhr[1]);
                    mma_bf16(sacc[nf2 * 2 + 1], qh[ks], bhr[2], bhr[3]);
                    mma_bf16(sacc[nf2 * 2],     qh[ks], blr[0], blr[1]);
                    mma_bf16(sacc[nf2 * 2 + 1], qh[ks], blr[2], blr[3]);
                    mma_bf16(sacc[nf2 * 2],     ql[ks], bhr[0], bhr[1]);
                    mma_bf16(sacc[nf2 * 2 + 1], ql[ks], bhr[2], bhr[3]);
                }
            }
            // ---- scale + causal mask ----
            const int r0g = qt * 128 + wid * 16 + (lane >> 2);
            const bool need_mask = (kt * 64 + 63) > (qt * 128 + wid * 16);
#pragma unroll
            for (int nf = 0; nf < 8; nf++)
#pragma unroll
                for (int c = 0; c < 4; c++) {
                    float v = sacc[nf][c] * 0.125f;
                    if (need_mask) {
                        const int col = kt * 64 + nf * 8 + (lane & 3) * 2 + (c & 1);
                        const int row = r0g + ((c >> 1) ? 8 : 0);
                        if (col > row) v = -1e30f;
                    }
                    sacc[nf][c] = v;
                }
            // ---- online softmax ----
            float mx0 = -1e30f, mx1 = -1e30f;
#pragma unroll
            for (int nf = 0; nf < 8; nf++) {
                mx0 = fmaxf(mx0, fmaxf(sacc[nf][0], sacc[nf][1]));
                mx1 = fmaxf(mx1, fmaxf(sacc[nf][2], sacc[nf][3]));
            }
            mx0 = fmaxf(mx0, __shfl_xor_sync(0xffffffffu, mx0, 1));
            mx0 = fmaxf(mx0, __shfl_xor_sync(0xffffffffu, mx0, 2));
            mx1 = fmaxf(mx1, __shfl_xor_sync(0xffffffffu, mx1, 1));
            mx1 = fmaxf(mx1, __shfl_xor_sync(0xffffffffu, mx1, 2));
            const float nm0 = fmaxf(m0, mx0);
            const float nm1 = fmaxf(m1, mx1);
            const float c0 = __expf(m0 - nm0);
            const float c1 = __expf(m1 - nm1);
            float s0 = 0.0f, s1 = 0.0f;
#pragma unroll
            for (int nf = 0; nf < 8; nf++) {
                float p0 = __expf(sacc[nf][0] - nm0);
                float p1 = __expf(sacc[nf][1] - nm0);
                float p2 = __expf(sacc[nf][2] - nm1);
                float p3 = __expf(sacc[nf][3] - nm1);
                sacc[nf][0] = p0; sacc[nf][1] = p1; sacc[nf][2] = p2; sacc[nf][3] = p3;
                s0 += p0 + p1; s1 += p2 + p3;
            }
            s0 += __shfl_xor_sync(0xffffffffu, s0, 1);
            s0 += __shfl_xor_sync(0xffffffffu, s0, 2);
            s1 += __shfl_xor_sync(0xffffffffu, s1, 1);
            s1 += __shfl_xor_sync(0xffffffffu, s1, 2);
            l0 = l0 * c0 + s0;
            l1 = l1 * c1 + s1;
            m0 = nm0; m1 = nm1;
#pragma unroll
            for (int nf = 0; nf < 8; nf++) {
                oacc[nf][0] *= c0; oacc[nf][1] *= c0;
                oacc[nf][2] *= c1; oacc[nf][3] *= c1;
            }
            // ---- pack P hi/lo A-fragments ----
            uint32_t ph[4][4], pl[4][4];
#pragma unroll
            for (int kb = 0; kb < 4; kb++) {
                hilo2(sacc[2 * kb][0],     sacc[2 * kb][1],     ph[kb][0], pl[kb][0]);
                hilo2(sacc[2 * kb][2],     sacc[2 * kb][3],     ph[kb][1], pl[kb][1]);
                hilo2(sacc[2 * kb + 1][0], sacc[2 * kb + 1][1], ph[kb][2], pl[kb][2]);
                hilo2(sacc[2 * kb + 1][2], sacc[2 * kb + 1][3], ph[kb][3], pl[kb][3]);
            }
            // ---- O += P V (3-term) ----
#pragma unroll
            for (int kb = 0; kb < 4; kb++) {
#pragma unroll
                for (int g = 0; g < 4; g++) {
                    uint32_t vh_[4], vl_[4];
                    const uint32_t off = (kb * 16 + v_row) * AP + (g * 16 + v_c8) * 2;
                    ldmx4t(vh_, vHiB + off);
                    ldmx4t(vl_, vLoB + off);
                    mma_bf16(oacc[g * 2],     ph[kb], vh_[0], vh_[1]);
                    mma_bf16(oacc[g * 2 + 1], ph[kb], vh_[2], vh_[3]);
                    mma_bf16(oacc[g * 2],     ph[kb], vl_[0], vl_[1]);
                    mma_bf16(oacc[g * 2 + 1], ph[kb], vl_[2], vl_[3]);
                    mma_bf16(oacc[g * 2],     pl[kb], vh_[0], vh_[1]);
                    mma_bf16(oacc[g * 2 + 1], pl[kb], vh_[2], vh_[3]);
                }
            }
        }
        __syncthreads();
    }

    // ---- normalize & write bf16 hi/lo to (B,L,D) ----
    const float inv0 = 1.0f / l0;
    const float inv1 = 1.0f / l1;
    const int b = bh >> 4;
    const int h = bh & 15;
    const int r0 = qt * 128 + wid * 16 + (lane >> 2);
#pragma unroll
    for (int nf = 0; nf < 8; nf++) {
        const int col = h * HD + nf * 8 + (lane & 3) * 2;
        {
            const size_t idx = (size_t)(b * LSEQ + r0) * BDIM + col;
            uint32_t hi, lo;
            hilo2(oacc[nf][0] * inv0, oacc[nf][1] * inv0, hi, lo);
            *reinterpret_cast<uint32_t*>(yhi + idx) = hi;
            *reinterpret_cast<uint32_t*>(ylo + idx) = lo;
        }
        {
            const size_t idx = (size_t)(b * LSEQ + r0 + 8) * BDIM + col;
            uint32_t hi, lo;
            hilo2(oacc[nf][2] * inv1, oacc[nf][3] * inv1, hi, lo);
            *reinterpret_cast<uint32_t*>(yhi + idx) = hi;
            *reinterpret_cast<uint32_t*>(ylo + idx) = lo;
        }
    }
}

// ---------------------------------------------------------------------------
extern "C" void kernel_launch(void* const* d_in, const int* in_sizes, int n_in,
                              void* d_out, int out_size) {
    const float* key   = (const float*)d_in[0];
    const float* value = (const float*)d_in[1];
    const float* query = (const float*)d_in[2];
    const float* Wk    = (const float*)d_in[3];
    const float* bk    = (const float*)d_in[4];
    const float* Wq    = (const float*)d_in[5];
    const float* bq    = (const float*)d_in[6];
    const float* Wv    = (const float*)d_in[7];
    const float* bv    = (const float*)d_in[8];
    const float* Wp    = (const float*)d_in[9];
    const float* bp    = (const float*)d_in[10];
    float* out = (float*)d_out;

    __nv_bfloat16 *qhi, *qlo, *khi, *klo, *vhi, *vlo, *ahi, *alo, *whi, *wlo;
    cudaGetSymbolAddress((void**)&qhi, g_qhi);
    cudaGetSymbolAddress((void**)&qlo, g_qlo);
    cudaGetSymbolAddress((void**)&khi, g_khi);
    cudaGetSymbolAddress((void**)&klo, g_klo);
    cudaGetSymbolAddress((void**)&vhi, g_vhi);
    cudaGetSymbolAddress((void**)&vlo, g_vlo);
    cudaGetSymbolAddress((void**)&ahi, g_ahi);
    cudaGetSymbolAddress((void**)&alo, g_alo);
    cudaGetSymbolAddress((void**)&whi, g_whi);
    cudaGetSymbolAddress((void**)&wlo, g_wlo);

    cudaFuncSetAttribute(gemm_mma<1>, cudaFuncAttributeMaxDynamicSharedMemorySize, GEMM_SMEM);
    cudaFuncSetAttribute(gemm_mma<0>, cudaFuncAttributeMaxDynamicSharedMemorySize, GEMM_SMEM);
    cudaFuncSetAttribute(attn_mma, cudaFuncAttributeMaxDynamicSharedMemorySize, ATTN_SMEM);

    const int nA4 = MROWS * BDIM / 4;
    const int nW4 = BDIM * BDIM / 4;
    dim3 gG(BDIM / 128, MROWS / 128);   // (8, 64)

    // Q projection -> bf16 hi/lo heads layout
    convert_hilo<<<nA4 / 256, 256>>>(query, ahi, alo, nA4);
    convert_hilo<<<nW4 / 256, 256>>>(Wq, whi, wlo, nW4);
    gemm_mma<1><<<gG, 256, GEMM_SMEM>>>(ahi, alo, whi, wlo, bq, nullptr, qhi, qlo);
    // K projection
    convert_hilo<<<nA4 / 256, 256>>>(key, ahi, alo, nA4);
    convert_hilo<<<nW4 / 256, 256>>>(Wk, whi, wlo, nW4);
    gemm_mma<1><<<gG, 256, GEMM_SMEM>>>(ahi, alo, whi, wlo, bk, nullptr, khi, klo);
    // V projection
    convert_hilo<<<nA4 / 256, 256>>>(value, ahi, alo, nA4);
    convert_hilo<<<nW4 / 256, 256>>>(Wv, whi, wlo, nW4);
    gemm_mma<1><<<gG, 256, GEMM_SMEM>>>(ahi, alo, whi, wlo, bv, nullptr, vhi, vlo);

    // Attention (HMMA, 3-term hi/lo) -> writes ahi/alo in (B,L,D)
    dim3 gA(LSEQ / 128, BATCH * HEADS);  // (8, 128)
    attn_mma<<<gA, 256, ATTN_SMEM>>>(qhi, qlo, khi, klo, vhi, vlo, ahi, alo);

    // Output projection (fp32 out)
    convert_hilo<<<nW4 / 256, 256>>>(Wp, whi, wlo, nW4);
    gemm_mma<0><<<gG, 256, GEMM_SMEM>>>(ahi, alo, whi, wlo, bp, out, nullptr, nullptr);
}

// round 6
// speedup vs baseline: 6.2704x; 2.4222x over previous
#include <cuda_runtime.h>
#include <cuda_fp16.h>
#include <cstdint>

#define BDIM  1024
#define HEADS 16
#define HD    64
#define LSEQ  1024
#define BATCH 8
#define MROWS (BATCH * LSEQ)   // 8192

// ---------------------------------------------------------------------------
// Scratch (__device__ globals; allocation-free rule)
// ---------------------------------------------------------------------------
__device__ __half g_q[BATCH * HEADS * LSEQ * HD];
__device__ __half g_k[BATCH * HEADS * LSEQ * HD];
__device__ __half g_v[BATCH * HEADS * LSEQ * HD];
__device__ __half g_a[MROWS * BDIM];     // converted activations / attn output
__device__ __half g_w[BDIM * BDIM];      // converted weights

// ---------------------------------------------------------------------------
// PTX helpers (base-target only)
// ---------------------------------------------------------------------------
__device__ __forceinline__ uint32_t smem_u32(const void* p) {
    uint32_t a;
    asm("{ .reg .u64 t; cvta.to.shared.u64 t, %1; cvt.u32.u64 %0, t; }" : "=r"(a) : "l"(p));
    return a;
}
__device__ __forceinline__ void ldmx4(uint32_t r[4], uint32_t a) {
    asm volatile("ldmatrix.sync.aligned.m8n8.x4.shared.b16 {%0,%1,%2,%3}, [%4];"
                 : "=r"(r[0]), "=r"(r[1]), "=r"(r[2]), "=r"(r[3]) : "r"(a));
}
__device__ __forceinline__ void ldmx4t(uint32_t r[4], uint32_t a) {
    asm volatile("ldmatrix.sync.aligned.m8n8.x4.trans.shared.b16 {%0,%1,%2,%3}, [%4];"
                 : "=r"(r[0]), "=r"(r[1]), "=r"(r[2]), "=r"(r[3]) : "r"(a));
}
__device__ __forceinline__ void mma_f16(float c[4], const uint32_t a[4],
                                        uint32_t b0, uint32_t b1) {
    asm volatile(
        "mma.sync.aligned.m16n8k16.row.col.f32.f16.f16.f32 "
        "{%0,%1,%2,%3}, {%4,%5,%6,%7}, {%8,%9}, {%0,%1,%2,%3};"
        : "+f"(c[0]), "+f"(c[1]), "+f"(c[2]), "+f"(c[3])
        : "r"(a[0]), "r"(a[1]), "r"(a[2]), "r"(a[3]), "r"(b0), "r"(b1));
}
__device__ __forceinline__ void cp16(uint32_t s, const void* g) {
    asm volatile("cp.async.cg.shared.global [%0], [%1], 16;" :: "r"(s), "l"(g));
}
__device__ __forceinline__ uint32_t pack2(float x, float y) {
    __half2 h = __floats2half2_rn(x, y);     // .x = low half = even element
    return *reinterpret_cast<uint32_t*>(&h);
}

// ---------------------------------------------------------------------------
// fp32 -> fp16 convert
// ---------------------------------------------------------------------------
__global__ __launch_bounds__(256) void convert_f16(const float* __restrict__ src,
                                                   __half* __restrict__ dst, int n4) {
    int i = blockIdx.x * blockDim.x + threadIdx.x;
    if (i >= n4) return;
    float4 v = reinterpret_cast<const float4*>(src)[i];
    uint2 u;
    u.x = pack2(v.x, v.y);
    u.y = pack2(v.z, v.w);
    reinterpret_cast<uint2*>(dst)[i] = u;
}

// ---------------------------------------------------------------------------
// HMMA fp16 GEMM: C[m][n] = sum_k A[m][k]*W[n][k] + bias[n]
// A (8192 x 1024), W (1024 x 1024) f16 K-major. CTA 128x128, K-chunk 32,
// cp.async double buffer, 8 warps (64x32 each), fp32 accum.
// smem rows: 32 halfs (64B) + 16B pad = 80B pitch.
// MODE 1: f16 out to (B,H,L,hd).  MODE 0: fp32 out (M,N).
// ---------------------------------------------------------------------------
#define TILE_B     (128 * 80)            // 10240
#define BUF_B      (2 * TILE_B)          // 20480
#define GEMM_SMEM  (2 * BUF_B)           // 40960

template <int MODE>
__global__ __launch_bounds__(256) void gemm_mma(const __half* __restrict__ A,
                                                const __half* __restrict__ W,
                                                const float* __restrict__ bias,
                                                float* __restrict__ C,
                                                __half* __restrict__ Ch) {
    extern __shared__ char smem[];
    const uint32_t sbase = smem_u32(smem);
    const int tid = threadIdx.x;
    const int wid = tid >> 5;
    const int lane = tid & 31;
    const int m0 = blockIdx.y * 128;
    const int n0 = blockIdx.x * 128;

    const __half* srcs[2] = {A + (size_t)m0 * BDIM, W + (size_t)n0 * BDIM};

    // 2 tiles x 128 rows x 4 segs(16B) = 1024 transfers, 4 per thread
    auto issue = [&](int c) {
        const int koff = c * 32;
        const uint32_t dbase = sbase + (c & 1) * BUF_B;
#pragma unroll
        for (int t = 0; t < 4; t++) {
            const int gid = t * 256 + tid;
            const int tile = gid >> 9;
            const int id = gid & 511;
            const int row = id >> 2;
            const int seg = id & 3;
            cp16(dbase + tile * TILE_B + row * 80 + seg * 16,
                 srcs[tile] + row * BDIM + koff + seg * 8);
        }
        asm volatile("cp.async.commit_group;");
    };

    const int warp_m = (wid >> 2) * 64;
    const int warp_n = (wid & 3) * 32;
    const int a_row = warp_m + (lane & 15);
    const int a_k8  = (lane >> 4) * 8;
    const int b_row = warp_n + (lane & 7) + ((lane >> 4) << 3);
    const int b_k8  = ((lane >> 3) & 1) * 8;

    float acc[4][4][4] = {};

    issue(0);
    for (int c = 0; c < 32; c++) {
        if (c + 1 < 32) {
            issue(c + 1);
            asm volatile("cp.async.wait_group 1;" ::: "memory");
        } else {
            asm volatile("cp.async.wait_group 0;" ::: "memory");
        }
        __syncthreads();
        const uint32_t bb = sbase + (c & 1) * BUF_B;
        const uint32_t aB = bb;
        const uint32_t wB = bb + TILE_B;
#pragma unroll
        for (int ks = 0; ks < 2; ks++) {
            const int kc = ks * 16;
            uint32_t ra[4][4];
#pragma unroll
            for (int mf = 0; mf < 4; mf++)
                ldmx4(ra[mf], aB + (a_row + mf * 16) * 80 + (kc + a_k8) * 2);
            uint32_t rb[2][4];
#pragma unroll
            for (int nf2 = 0; nf2 < 2; nf2++)
                ldmx4(rb[nf2], wB + (b_row + nf2 * 16) * 80 + (kc + b_k8) * 2);
#pragma unroll
            for (int mf = 0; mf < 4; mf++)
#pragma unroll
                for (int nf = 0; nf < 4; nf++)
                    mma_f16(acc[mf][nf], ra[mf],
                            rb[nf >> 1][(nf & 1) * 2], rb[nf >> 1][(nf & 1) * 2 + 1]);
        }
        __syncthreads();
    }

#pragma unroll
    for (int mf = 0; mf < 4; mf++) {
        const int mA = m0 + warp_m + mf * 16 + (lane >> 2);
#pragma unroll
        for (int nf = 0; nf < 4; nf++) {
            const int n = n0 + warp_n + nf * 8 + (lane & 3) * 2;
            const float2 bv = *reinterpret_cast<const float2*>(bias + n);
#pragma unroll
            for (int half = 0; half < 2; half++) {
                const int m = mA + half * 8;
                const float ox = acc[mf][nf][half * 2 + 0] + bv.x;
                const float oy = acc[mf][nf][half * 2 + 1] + bv.y;
                if (MODE == 1) {
                    const int b = m >> 10;
                    const int l = m & 1023;
                    const int h = n >> 6;
                    const int cc = n & 63;
                    const size_t idx = (size_t)(((b * HEADS + h) * LSEQ) + l) * HD + cc;
                    *reinterpret_cast<uint32_t*>(Ch + idx) = pack2(ox, oy);
                } else {
                    float2 out = {ox, oy};
                    *reinterpret_cast<float2*>(C + (size_t)m * BDIM + n) = out;
                }
            }
        }
    }
}

// ---------------------------------------------------------------------------
// HMMA fp16 flash attention: Br=128, Bc=64, hd=64, causal, fp32 softmax.
// Grid (L/128, B*H), 256 threads (8 warps; warp w owns q rows w*16..w*16+15).
// Attention rows are FULL hd=64 halfs = 128B; pitch AP=144B (128 + 16 pad).
// ---------------------------------------------------------------------------
#define AP     144
#define QT_B   (128 * AP)               // 18432
#define KVT_B  (64 * AP)                // 9216
#define KVS_B  (2 * KVT_B)              // 18432 per stage (K + V)
#define ATTN_SMEM (QT_B + 2 * KVS_B)    // 55296

__global__ __launch_bounds__(256) void attn_mma(
    const __half* __restrict__ qf, const __half* __restrict__ kf,
    const __half* __restrict__ vf, __half* __restrict__ yf) {
    extern __shared__ char smem[];
    const uint32_t sb = smem_u32(smem);
    const int tid = threadIdx.x;
    const int wid = tid >> 5;
    const int lane = tid & 31;
    const int qt = blockIdx.x;
    const int bh = blockIdx.y;
    const size_t hoff = (size_t)bh * LSEQ * HD;

    const __half* qsrc = qf + hoff;
    const __half* kvsrc[2] = {kf + hoff, vf + hoff};

    // Q tile: 128 rows x 8 segs(16B) = 1024 cp16, 4 per thread
#pragma unroll
    for (int t = 0; t < 4; t++) {
        const int gid = t * 256 + tid;
        const int row = gid >> 3;
        const int seg = gid & 7;
        cp16(sb + row * AP + seg * 16,
             qsrc + (size_t)(qt * 128 + row) * HD + seg * 8);
    }
    auto issue_kv = [&](int kt) {
        const uint32_t dbase = sb + QT_B + (kt & 1) * KVS_B;
#pragma unroll
        for (int t = 0; t < 4; t++) {
            const int gid = t * 256 + tid;
            const int tile = gid >> 9;       // 0 = K, 1 = V
            const int id = gid & 511;
            const int row = id >> 3;         // 0..63
            const int seg = id & 7;
            cp16(dbase + tile * KVT_B + row * AP + seg * 16,
                 kvsrc[tile] + (size_t)(kt * 64 + row) * HD + seg * 8);
        }
        asm volatile("cp.async.commit_group;");
    };
    issue_kv(0);   // group 0 = Q + KV0

    const int a_row = wid * 16 + (lane & 15);
    const int a_k8  = (lane >> 4) * 8;
    const int b_row = (lane & 7) + ((lane >> 4) << 3);
    const int b_k8  = ((lane >> 3) & 1) * 8;
    const int v_row = lane & 15;
    const int v_c8  = (lane >> 4) * 8;

    uint32_t qh[4][4];
    float oacc[8][4] = {};
    float m0 = -1e30f, m1 = -1e30f, l0 = 0.0f, l1 = 0.0f;

    const int ktmax = 2 * qt + 1;
    for (int kt = 0; kt <= ktmax; kt++) {
        if (kt < ktmax) {
            issue_kv(kt + 1);
            asm volatile("cp.async.wait_group 1;" ::: "memory");
        } else {
            asm volatile("cp.async.wait_group 0;" ::: "memory");
        }
        __syncthreads();
        if (kt == 0) {
#pragma unroll
            for (int ks = 0; ks < 4; ks++)
                ldmx4(qh[ks], sb + a_row * AP + (ks * 16 + a_k8) * 2);
        }
        const bool skip = (kt * 64) > (qt * 128 + wid * 16 + 15);
        if (!skip) {
            const uint32_t kB = sb + QT_B + (kt & 1) * KVS_B;
            const uint32_t vB = kB + KVT_B;

            // ---- S = Q K^T ----
            float sacc[8][4] = {};
#pragma unroll
            for (int ks = 0; ks < 4; ks++) {
#pragma unroll
                for (int nf2 = 0; nf2 < 4; nf2++) {
                    uint32_t br[4];
                    ldmx4(br, kB + (nf2 * 16 + b_row) * AP + (ks * 16 + b_k8) * 2);
                    mma_f16(sacc[nf2 * 2],     qh[ks], br[0], br[1]);
                    mma_f16(sacc[nf2 * 2 + 1], qh[ks], br[2], br[3]);
                }
            }
            // ---- scale + causal mask ----
            const int r0g = qt * 128 + wid * 16 + (lane >> 2);
            const bool need_mask = (kt * 64 + 63) > (qt * 128 + wid * 16);
#pragma unroll
            for (int nf = 0; nf < 8; nf++)
#pragma unroll
                for (int c = 0; c < 4; c++) {
                    float v = sacc[nf][c] * 0.125f;
                    if (need_mask) {
                        const int col = kt * 64 + nf * 8 + (lane & 3) * 2 + (c & 1);
                        const int row = r0g + ((c >> 1) ? 8 : 0);
                        if (col > row) v = -1e30f;
                    }
                    sacc[nf][c] = v;
                }
            // ---- online softmax ----
            float mx0 = -1e30f, mx1 = -1e30f;
#pragma unroll
            for (int nf = 0; nf < 8; nf++) {
                mx0 = fmaxf(mx0, fmaxf(sacc[nf][0], sacc[nf][1]));
                mx1 = fmaxf(mx1, fmaxf(sacc[nf][2], sacc[nf][3]));
            }
            mx0 = fmaxf(mx0, __shfl_xor_sync(0xffffffffu, mx0, 1));
            mx0 = fmaxf(mx0, __shfl_xor_sync(0xffffffffu, mx0, 2));
            mx1 = fmaxf(mx1, __shfl_xor_sync(0xffffffffu, mx1, 1));
            mx1 = fmaxf(mx1, __shfl_xor_sync(0xffffffffu, mx1, 2));
            const float nm0 = fmaxf(m0, mx0);
            const float nm1 = fmaxf(m1, mx1);
            const float c0 = __expf(m0 - nm0);
            const float c1 = __expf(m1 - nm1);
            float s0 = 0.0f, s1 = 0.0f;
#pragma unroll
            for (int nf = 0; nf < 8; nf++) {
                float p0 = __expf(sacc[nf][0] - nm0);
                float p1 = __expf(sacc[nf][1] - nm0);
                float p2 = __expf(sacc[nf][2] - nm1);
                float p3 = __expf(sacc[nf][3] - nm1);
                sacc[nf][0] = p0; sacc[nf][1] = p1; sacc[nf][2] = p2; sacc[nf][3] = p3;
                s0 += p0 + p1; s1 += p2 + p3;
            }
            s0 += __shfl_xor_sync(0xffffffffu, s0, 1);
            s0 += __shfl_xor_sync(0xffffffffu, s0, 2);
            s1 += __shfl_xor_sync(0xffffffffu, s1, 1);
            s1 += __shfl_xor_sync(0xffffffffu, s1, 2);
            l0 = l0 * c0 + s0;
            l1 = l1 * c1 + s1;
            m0 = nm0; m1 = nm1;
#pragma unroll
            for (int nf = 0; nf < 8; nf++) {
                oacc[nf][0] *= c0; oacc[nf][1] *= c0;
                oacc[nf][2] *= c1; oacc[nf][3] *= c1;
            }
            // ---- pack P A-fragments (f16) ----
            uint32_t ph[4][4];
#pragma unroll
            for (int kb = 0; kb < 4; kb++) {
                ph[kb][0] = pack2(sacc[2 * kb][0],     sacc[2 * kb][1]);
                ph[kb][1] = pack2(sacc[2 * kb][2],     sacc[2 * kb][3]);
                ph[kb][2] = pack2(sacc[2 * kb + 1][0], sacc[2 * kb + 1][1]);
                ph[kb][3] = pack2(sacc[2 * kb + 1][2], sacc[2 * kb + 1][3]);
            }
            // ---- O += P V ----
#pragma unroll
            for (int kb = 0; kb < 4; kb++) {
#pragma unroll
                for (int g = 0; g < 4; g++) {
                    uint32_t vr[4];
                    ldmx4t(vr, vB + (kb * 16 + v_row) * AP + (g * 16 + v_c8) * 2);
                    mma_f16(oacc[g * 2],     ph[kb], vr[0], vr[1]);
                    mma_f16(oacc[g * 2 + 1], ph[kb], vr[2], vr[3]);
                }
            }
        }
        __syncthreads();
    }

    // ---- normalize & write f16 to (B,L,D) ----
    const float inv0 = 1.0f / l0;
    const float inv1 = 1.0f / l1;
    const int b = bh >> 4;
    const int h = bh & 15;
    const int r0 = qt * 128 + wid * 16 + (lane >> 2);
#pragma unroll
    for (int nf = 0; nf < 8; nf++) {
        const int col = h * HD + nf * 8 + (lane & 3) * 2;
        *reinterpret_cast<uint32_t*>(yf + (size_t)(b * LSEQ + r0) * BDIM + col) =
            pack2(oacc[nf][0] * inv0, oacc[nf][1] * inv0);
        *reinterpret_cast<uint32_t*>(yf + (size_t)(b * LSEQ + r0 + 8) * BDIM + col) =
            pack2(oacc[nf][2] * inv1, oacc[nf][3] * inv1);
    }
}

// ---------------------------------------------------------------------------
extern "C" void kernel_launch(void* const* d_in, const int* in_sizes, int n_in,
                              void* d_out, int out_size) {
    const float* key   = (const float*)d_in[0];
    const float* value = (const float*)d_in[1];
    const float* query = (const float*)d_in[2];
    const float* Wk    = (const float*)d_in[3];
    const float* bk    = (const float*)d_in[4];
    const float* Wq    = (const float*)d_in[5];
    const float* bq    = (const float*)d_in[6];
    const float* Wv    = (const float*)d_in[7];
    const float* bv    = (const float*)d_in[8];
    const float* Wp    = (const float*)d_in[9];
    const float* bp    = (const float*)d_in[10];
    float* out = (float*)d_out;

    __half *qf, *kf, *vf, *af, *wf;
    cudaGetSymbolAddress((void**)&qf, g_q);
    cudaGetSymbolAddress((void**)&kf, g_k);
    cudaGetSymbolAddress((void**)&vf, g_v);
    cudaGetSymbolAddress((void**)&af, g_a);
    cudaGetSymbolAddress((void**)&wf, g_w);

    cudaFuncSetAttribute(gemm_mma<1>, cudaFuncAttributeMaxDynamicSharedMemorySize, GEMM_SMEM);
    cudaFuncSetAttribute(gemm_mma<0>, cudaFuncAttributeMaxDynamicSharedMemorySize, GEMM_SMEM);
    cudaFuncSetAttribute(attn_mma, cudaFuncAttributeMaxDynamicSharedMemorySize, ATTN_SMEM);

    const int nA4 = MROWS * BDIM / 4;
    const int nW4 = BDIM * BDIM / 4;
    dim3 gG(BDIM / 128, MROWS / 128);   // (8, 64)

    // Q projection
    convert_f16<<<nA4 / 256, 256>>>(query, af, nA4);
    convert_f16<<<nW4 / 256, 256>>>(Wq, wf, nW4);
    gemm_mma<1><<<gG, 256, GEMM_SMEM>>>(af, wf, bq, nullptr, qf);
    // K projection
    convert_f16<<<nA4 / 256, 256>>>(key, af, nA4);
    convert_f16<<<nW4 / 256, 256>>>(Wk, wf, nW4);
    gemm_mma<1><<<gG, 256, GEMM_SMEM>>>(af, wf, bk, nullptr, kf);
    // V projection
    convert_f16<<<nA4 / 256, 256>>>(value, af, nA4);
    convert_f16<<<nW4 / 256, 256>>>(Wv, wf, nW4);
    gemm_mma<1><<<gG, 256, GEMM_SMEM>>>(af, wf, bv, nullptr, vf);

    // Attention -> af (f16, (B,L,D))
    dim3 gA(LSEQ / 128, BATCH * HEADS);  // (8, 128)
    attn_mma<<<gA, 256, ATTN_SMEM>>>(qf, kf, vf, af);

    // Output projection (fp32 out)
    convert_f16<<<nW4 / 256, 256>>>(Wp, wf, nW4);
    gemm_mma<0><<<gG, 256, GEMM_SMEM>>>(af, wf, bp, out, nullptr);
}

// round 7
// speedup vs baseline: 7.1169x; 1.1350x over previous
#include <cuda_runtime.h>
#include <cuda_fp16.h>
#include <cstdint>

#define BDIM  1024
#define HEADS 16
#define HD    64
#define LSEQ  1024
#define BATCH 8
#define MROWS (BATCH * LSEQ)   // 8192
#define ACT_SZ  ((size_t)MROWS * BDIM)          // 8M halfs
#define WT_SZ   ((size_t)BDIM * BDIM)           // 1M halfs
#define QKV_SZ  ((size_t)BATCH * HEADS * LSEQ * HD)

// ---------------------------------------------------------------------------
// Scratch (__device__ globals; allocation-free rule)
// ---------------------------------------------------------------------------
__device__ __half g_act[3 * ACT_SZ];    // f16 query/key/value activations
__device__ __half g_wt[4 * WT_SZ];      // f16 Wq/Wk/Wv/Wp
__device__ __half g_qkv[3 * QKV_SZ];    // f16 Q/K/V in (B,H,L,hd)
__device__ __half g_y[ACT_SZ];          // f16 attention output (B,L,D)

// ---------------------------------------------------------------------------
// PTX helpers (base-target only)
// ---------------------------------------------------------------------------
__device__ __forceinline__ uint32_t smem_u32(const void* p) {
    uint32_t a;
    asm("{ .reg .u64 t; cvta.to.shared.u64 t, %1; cvt.u32.u64 %0, t; }" : "=r"(a) : "l"(p));
    return a;
}
__device__ __forceinline__ void ldmx4(uint32_t r[4], uint32_t a) {
    asm volatile("ldmatrix.sync.aligned.m8n8.x4.shared.b16 {%0,%1,%2,%3}, [%4];"
                 : "=r"(r[0]), "=r"(r[1]), "=r"(r[2]), "=r"(r[3]) : "r"(a));
}
__device__ __forceinline__ void ldmx4t(uint32_t r[4], uint32_t a) {
    asm volatile("ldmatrix.sync.aligned.m8n8.x4.trans.shared.b16 {%0,%1,%2,%3}, [%4];"
                 : "=r"(r[0]), "=r"(r[1]), "=r"(r[2]), "=r"(r[3]) : "r"(a));
}
__device__ __forceinline__ void mma_f16(float c[4], const uint32_t a[4],
                                        uint32_t b0, uint32_t b1) {
    asm volatile(
        "mma.sync.aligned.m16n8k16.row.col.f32.f16.f16.f32 "
        "{%0,%1,%2,%3}, {%4,%5,%6,%7}, {%8,%9}, {%0,%1,%2,%3};"
        : "+f"(c[0]), "+f"(c[1]), "+f"(c[2]), "+f"(c[3])
        : "r"(a[0]), "r"(a[1]), "r"(a[2]), "r"(a[3]), "r"(b0), "r"(b1));
}
__device__ __forceinline__ void cp16(uint32_t s, const void* g) {
    asm volatile("cp.async.cg.shared.global [%0], [%1], 16;" :: "r"(s), "l"(g));
}
__device__ __forceinline__ uint32_t pack2(float x, float y) {
    __half2 h = __floats2half2_rn(x, y);     // .x = low half = even element
    return *reinterpret_cast<uint32_t*>(&h);
}

// ---------------------------------------------------------------------------
// Batched fp32 -> fp16 converts
// ---------------------------------------------------------------------------
__global__ __launch_bounds__(256) void convert_acts(const float* __restrict__ q,
                                                    const float* __restrict__ k,
                                                    const float* __restrict__ v,
                                                    __half* __restrict__ dst, int n4) {
    const int t = blockIdx.y;
    const float* src = (t == 0) ? q : (t == 1) ? k : v;
    __half* d = dst + (size_t)t * ACT_SZ;
    int i = blockIdx.x * blockDim.x + threadIdx.x;
    if (i >= n4) return;
    float4 vv = reinterpret_cast<const float4*>(src)[i];
    uint2 u;
    u.x = pack2(vv.x, vv.y);
    u.y = pack2(vv.z, vv.w);
    reinterpret_cast<uint2*>(d)[i] = u;
}

__global__ __launch_bounds__(256) void convert_wts(const float* __restrict__ w0,
                                                   const float* __restrict__ w1,
                                                   const float* __restrict__ w2,
                                                   const float* __restrict__ w3,
                                                   __half* __restrict__ dst, int n4) {
    const int t = blockIdx.y;
    const float* src = (t == 0) ? w0 : (t == 1) ? w1 : (t == 2) ? w2 : w3;
    __half* d = dst + (size_t)t * WT_SZ;
    int i = blockIdx.x * blockDim.x + threadIdx.x;
    if (i >= n4) return;
    float4 vv = reinterpret_cast<const float4*>(src)[i];
    uint2 u;
    u.x = pack2(vv.x, vv.y);
    u.y = pack2(vv.z, vv.w);
    reinterpret_cast<uint2*>(d)[i] = u;
}

// ---------------------------------------------------------------------------
// HMMA fp16 GEMM: C[m][n] = sum_k A[m][k]*W[n][k] + bias[n]
// 4-stage cp.async pipeline, ONE __syncthreads per K-chunk.
// grid.z selects (A, W, bias, output) tensor set.
// MODE 1: f16 out to (B,H,L,hd) (z in 0..2). MODE 0: fp32 out (M,N), z=0.
// ---------------------------------------------------------------------------
#define TILE_B     (128 * 80)            // 10240
#define BUF_B      (2 * TILE_B)          // 20480 per stage
#define GEMM_SMEM  (4 * BUF_B)           // 81920 (4 stages)

template <int MODE>
__global__ __launch_bounds__(256) void gemm_mma(const __half* __restrict__ A0,
                                                const __half* __restrict__ W0,
                                                const float* __restrict__ b0,
                                                const float* __restrict__ b1,
                                                const float* __restrict__ b2,
                                                float* __restrict__ C,
                                                __half* __restrict__ Ch0) {
    extern __shared__ char smem[];
    const uint32_t sbase = smem_u32(smem);
    const int tid = threadIdx.x;
    const int wid = tid >> 5;
    const int lane = tid & 31;
    const int z = blockIdx.z;
    const int m0 = blockIdx.y * 128;
    const int n0 = blockIdx.x * 128;

    const __half* A = A0 + (size_t)z * ACT_SZ;
    const __half* W = W0 + (size_t)z * WT_SZ;
    const float* bias = (z == 0) ? b0 : (z == 1) ? b1 : b2;
    __half* Ch = Ch0 + (size_t)z * QKV_SZ;

    const __half* srcs[2] = {A + (size_t)m0 * BDIM, W + (size_t)n0 * BDIM};

    auto issue = [&](int c) {
        const int koff = c * 32;
        const uint32_t dbase = sbase + (c & 3) * BUF_B;
#pragma unroll
        for (int t = 0; t < 4; t++) {
            const int gid = t * 256 + tid;
            const int tile = gid >> 9;
            const int id = gid & 511;
            const int row = id >> 2;
            const int seg = id & 3;
            cp16(dbase + tile * TILE_B + row * 80 + seg * 16,
                 srcs[tile] + row * BDIM + koff + seg * 8);
        }
        asm volatile("cp.async.commit_group;");
    };

    const int warp_m = (wid >> 2) * 64;
    const int warp_n = (wid & 3) * 32;
    const int a_row = warp_m + (lane & 15);
    const int a_k8  = (lane >> 4) * 8;
    const int b_row = warp_n + (lane & 7) + ((lane >> 4) << 3);
    const int b_k8  = ((lane >> 3) & 1) * 8;

    float acc[4][4][4] = {};

    issue(0); issue(1); issue(2);
    for (int c = 0; c < 32; c++) {
        if (c < 30)       asm volatile("cp.async.wait_group 2;" ::: "memory");
        else if (c == 30) asm volatile("cp.async.wait_group 1;" ::: "memory");
        else              asm volatile("cp.async.wait_group 0;" ::: "memory");
        __syncthreads();
        const uint32_t bb = sbase + (c & 3) * BUF_B;
        const uint32_t aB = bb;
        const uint32_t wB = bb + TILE_B;
#pragma unroll
        for (int ks = 0; ks < 2; ks++) {
            const int kc = ks * 16;
            uint32_t ra[4][4];
#pragma unroll
            for (int mf = 0; mf < 4; mf++)
                ldmx4(ra[mf], aB + (a_row + mf * 16) * 80 + (kc + a_k8) * 2);
            uint32_t rb[2][4];
#pragma unroll
            for (int nf2 = 0; nf2 < 2; nf2++)
                ldmx4(rb[nf2], wB + (b_row + nf2 * 16) * 80 + (kc + b_k8) * 2);
#pragma unroll
            for (int mf = 0; mf < 4; mf++)
#pragma unroll
                for (int nf = 0; nf < 4; nf++)
                    mma_f16(acc[mf][nf], ra[mf],
                            rb[nf >> 1][(nf & 1) * 2], rb[nf >> 1][(nf & 1) * 2 + 1]);
        }
        if (c + 3 < 32) issue(c + 3);
    }

#pragma unroll
    for (int mf = 0; mf < 4; mf++) {
        const int mA = m0 + warp_m + mf * 16 + (lane >> 2);
#pragma unroll
        for (int nf = 0; nf < 4; nf++) {
            const int n = n0 + warp_n + nf * 8 + (lane & 3) * 2;
            const float2 bv = *reinterpret_cast<const float2*>(bias + n);
#pragma unroll
            for (int half = 0; half < 2; half++) {
                const int m = mA + half * 8;
                const float ox = acc[mf][nf][half * 2 + 0] + bv.x;
                const float oy = acc[mf][nf][half * 2 + 1] + bv.y;
                if (MODE == 1) {
                    const int b = m >> 10;
                    const int l = m & 1023;
                    const int h = n >> 6;
                    const int cc = n & 63;
                    const size_t idx = (size_t)(((b * HEADS + h) * LSEQ) + l) * HD + cc;
                    *reinterpret_cast<uint32_t*>(Ch + idx) = pack2(ox, oy);
                } else {
                    float2 out = {ox, oy};
                    *reinterpret_cast<float2*>(C + (size_t)m * BDIM + n) = out;
                }
            }
        }
    }
}

// ---------------------------------------------------------------------------
// HMMA fp16 flash attention: Br=128, Bc=64, hd=64, causal, fp32 softmax.
// 3-stage KV pipeline, ONE sync per tile, heavy CTAs (large qt) first.
// ---------------------------------------------------------------------------
#define AP     144
#define QT_B   (128 * AP)               // 18432
#define KVT_B  (64 * AP)                // 9216
#define KVS_B  (2 * KVT_B)              // 18432 per stage (K + V)
#define ATTN_SMEM (QT_B + 3 * KVS_B)    // 73728

__global__ __launch_bounds__(256) void attn_mma(
    const __half* __restrict__ qkv, __half* __restrict__ yf) {
    extern __shared__ char smem[];
    const uint32_t sb = smem_u32(smem);
    const int tid = threadIdx.x;
    const int wid = tid >> 5;
    const int lane = tid & 31;
    const int qt = gridDim.x - 1 - blockIdx.x;   // heavy tiles first
    const int bh = blockIdx.y;
    const size_t hoff = (size_t)bh * LSEQ * HD;

    const __half* qsrc = qkv + hoff;
    const __half* kvsrc[2] = {qkv + QKV_SZ + hoff, qkv + 2 * QKV_SZ + hoff};

    auto issue_kv = [&](int kt) {
        const uint32_t dbase = sb + QT_B + (kt % 3) * KVS_B;
#pragma unroll
        for (int t = 0; t < 4; t++) {
            const int gid = t * 256 + tid;
            const int tile = gid >> 9;       // 0 = K, 1 = V
            const int id = gid & 511;
            const int row = id >> 3;         // 0..63
            const int seg = id & 7;
            cp16(dbase + tile * KVT_B + row * AP + seg * 16,
                 kvsrc[tile] + (size_t)(kt * 64 + row) * HD + seg * 8);
        }
        asm volatile("cp.async.commit_group;");
    };

    // Q tile: 128 rows x 8 segs(16B); committed together with KV0 (group 0)
#pragma unroll
    for (int t = 0; t < 4; t++) {
        const int gid = t * 256 + tid;
        const int row = gid >> 3;
        const int seg = gid & 7;
        cp16(sb + row * AP + seg * 16,
             qsrc + (size_t)(qt * 128 + row) * HD + seg * 8);
    }
    issue_kv(0);      // group 0 = Q + KV0
    const int ktmax = 2 * qt + 1;
    if (1 <= ktmax) issue_kv(1);   // group 1

    const int a_row = wid * 16 + (lane & 15);
    const int a_k8  = (lane >> 4) * 8;
    const int b_row = (lane & 7) + ((lane >> 4) << 3);
    const int b_k8  = ((lane >> 3) & 1) * 8;
    const int v_row = lane & 15;
    const int v_c8  = (lane >> 4) * 8;

    uint32_t qh[4][4];
    float oacc[8][4] = {};
    float m0 = -1e30f, m1 = -1e30f, l0 = 0.0f, l1 = 0.0f;

    for (int kt = 0; kt <= ktmax; kt++) {
        if (kt < ktmax) asm volatile("cp.async.wait_group 1;" ::: "memory");
        else            asm volatile("cp.async.wait_group 0;" ::: "memory");
        __syncthreads();
        if (kt == 0) {
#pragma unroll
            for (int ks = 0; ks < 4; ks++)
                ldmx4(qh[ks], sb + a_row * AP + (ks * 16 + a_k8) * 2);
        }
        const bool skip = (kt * 64) > (qt * 128 + wid * 16 + 15);
        if (!skip) {
            const uint32_t kB = sb + QT_B + (kt % 3) * KVS_B;
            const uint32_t vB = kB + KVT_B;

            // ---- S = Q K^T ----
            float sacc[8][4] = {};
#pragma unroll
            for (int ks = 0; ks < 4; ks++) {
#pragma unroll
                for (int nf2 = 0; nf2 < 4; nf2++) {
                    uint32_t br[4];
                    ldmx4(br, kB + (nf2 * 16 + b_row) * AP + (ks * 16 + b_k8) * 2);
                    mma_f16(sacc[nf2 * 2],     qh[ks], br[0], br[1]);
                    mma_f16(sacc[nf2 * 2 + 1], qh[ks], br[2], br[3]);
                }
            }
            // ---- scale + causal mask ----
            const int r0g = qt * 128 + wid * 16 + (lane >> 2);
            const bool need_mask = (kt * 64 + 63) > (qt * 128 + wid * 16);
#pragma unroll
            for (int nf = 0; nf < 8; nf++)
#pragma unroll
                for (int c = 0; c < 4; c++) {
                    float v = sacc[nf][c] * 0.125f;
                    if (need_mask) {
                        const int col = kt * 64 + nf * 8 + (lane & 3) * 2 + (c & 1);
                        const int row = r0g + ((c >> 1) ? 8 : 0);
                        if (col > row) v = -1e30f;
                    }
                    sacc[nf][c] = v;
                }
            // ---- online softmax ----
            float mx0 = -1e30f, mx1 = -1e30f;
#pragma unroll
            for (int nf = 0; nf < 8; nf++) {
                mx0 = fmaxf(mx0, fmaxf(sacc[nf][0], sacc[nf][1]));
                mx1 = fmaxf(mx1, fmaxf(sacc[nf][2], sacc[nf][3]));
            }
            mx0 = fmaxf(mx0, __shfl_xor_sync(0xffffffffu, mx0, 1));
            mx0 = fmaxf(mx0, __shfl_xor_sync(0xffffffffu, mx0, 2));
            mx1 = fmaxf(mx1, __shfl_xor_sync(0xffffffffu, mx1, 1));
            mx1 = fmaxf(mx1, __shfl_xor_sync(0xffffffffu, mx1, 2));
            const float nm0 = fmaxf(m0, mx0);
            const float nm1 = fmaxf(m1, mx1);
            const float c0 = __expf(m0 - nm0);
            const float c1 = __expf(m1 - nm1);
            float s0 = 0.0f, s1 = 0.0f;
#pragma unroll
            for (int nf = 0; nf < 8; nf++) {
                float p0 = __expf(sacc[nf][0] - nm0);
                float p1 = __expf(sacc[nf][1] - nm0);
                float p2 = __expf(sacc[nf][2] - nm1);
                float p3 = __expf(sacc[nf][3] - nm1);
                sacc[nf][0] = p0; sacc[nf][1] = p1; sacc[nf][2] = p2; sacc[nf][3] = p3;
                s0 += p0 + p1; s1 += p2 + p3;
            }
            s0 += __shfl_xor_sync(0xffffffffu, s0, 1);
            s0 += __shfl_xor_sync(0xffffffffu, s0, 2);
            s1 += __shfl_xor_sync(0xffffffffu, s1, 1);
            s1 += __shfl_xor_sync(0xffffffffu, s1, 2);
            l0 = l0 * c0 + s0;
            l1 = l1 * c1 + s1;
            m0 = nm0; m1 = nm1;
#pragma unroll
            for (int nf = 0; nf < 8; nf++) {
                oacc[nf][0] *= c0; oacc[nf][1] *= c0;
                oacc[nf][2] *= c1; oacc[nf][3] *= c1;
            }
            // ---- pack P A-fragments (f16) ----
            uint32_t ph[4][4];
#pragma unroll
            for (int kb = 0; kb < 4; kb++) {
                ph[kb][0] = pack2(sacc[2 * kb][0],     sacc[2 * kb][1]);
                ph[kb][1] = pack2(sacc[2 * kb][2],     sacc[2 * kb][3]);
                ph[kb][2] = pack2(sacc[2 * kb + 1][0], sacc[2 * kb + 1][1]);
                ph[kb][3] = pack2(sacc[2 * kb + 1][2], sacc[2 * kb + 1][3]);
            }
            // ---- O += P V ----
#pragma unroll
            for (int kb = 0; kb < 4; kb++) {
#pragma unroll
                for (int g = 0; g < 4; g++) {
                    uint32_t vr[4];
                    ldmx4t(vr, vB + (kb * 16 + v_row) * AP + (g * 16 + v_c8) * 2);
                    mma_f16(oacc[g * 2],     ph[kb], vr[0], vr[1]);
                    mma_f16(oacc[g * 2 + 1], ph[kb], vr[2], vr[3]);
                }
            }
        }
        if (kt + 2 <= ktmax) issue_kv(kt + 2);
    }

    // ---- normalize & write f16 to (B,L,D) ----
    const float inv0 = 1.0f / l0;
    const float inv1 = 1.0f / l1;
    const int b = bh >> 4;
    const int h = bh & 15;
    const int r0 = qt * 128 + wid * 16 + (lane >> 2);
#pragma unroll
    for (int nf = 0; nf < 8; nf++) {
        const int col = h * HD + nf * 8 + (lane & 3) * 2;
        *reinterpret_cast<uint32_t*>(yf + (size_t)(b * LSEQ + r0) * BDIM + col) =
            pack2(oacc[nf][0] * inv0, oacc[nf][1] * inv0);
        *reinterpret_cast<uint32_t*>(yf + (size_t)(b * LSEQ + r0 + 8) * BDIM + col) =
            pack2(oacc[nf][2] * inv1, oacc[nf][3] * inv1);
    }
}

// ---------------------------------------------------------------------------
extern "C" void kernel_launch(void* const* d_in, const int* in_sizes, int n_in,
                              void* d_out, int out_size) {
    const float* key   = (const float*)d_in[0];
    const float* value = (const float*)d_in[1];
    const float* query = (const float*)d_in[2];
    const float* Wk    = (const float*)d_in[3];
    const float* bk    = (const float*)d_in[4];
    const float* Wq    = (const float*)d_in[5];
    const float* bq    = (const float*)d_in[6];
    const float* Wv    = (const float*)d_in[7];
    const float* bv    = (const float*)d_in[8];
    const float* Wp    = (const float*)d_in[9];
    const float* bp    = (const float*)d_in[10];
    float* out = (float*)d_out;

    __half *act, *wt, *qkv, *yf;
    cudaGetSymbolAddress((void**)&act, g_act);
    cudaGetSymbolAddress((void**)&wt, g_wt);
    cudaGetSymbolAddress((void**)&qkv, g_qkv);
    cudaGetSymbolAddress((void**)&yf, g_y);

    cudaFuncSetAttribute(gemm_mma<1>, cudaFuncAttributeMaxDynamicSharedMemorySize, GEMM_SMEM);
    cudaFuncSetAttribute(gemm_mma<0>, cudaFuncAttributeMaxDynamicSharedMemorySize, GEMM_SMEM);
    cudaFuncSetAttribute(attn_mma, cudaFuncAttributeMaxDynamicSharedMemorySize, ATTN_SMEM);

    const int nA4 = MROWS * BDIM / 4;
    const int nW4 = BDIM * BDIM / 4;

    // All converts in 2 launches (act order matches gemm z: 0=query,1=key,2=value)
    convert_acts<<<dim3(nA4 / 256, 3), 256>>>(query, key, value, act, nA4);
    convert_wts<<<dim3(nW4 / 256, 4), 256>>>(Wq, Wk, Wv, Wp, wt, nW4);

    // Fused Q/K/V projections (z = 0,1,2)
    dim3 gG3(BDIM / 128, MROWS / 128, 3);
    gemm_mma<1><<<gG3, 256, GEMM_SMEM>>>(act, wt, bq, bk, bv, nullptr, qkv);

    // Attention -> yf (f16, (B,L,D))
    dim3 gA(LSEQ / 128, BATCH * HEADS);
    attn_mma<<<gA, 256, ATTN_SMEM>>>(qkv, yf);

    // Output projection (fp32 out); A = yf, W = wt[3]
    dim3 gG(BDIM / 128, MROWS / 128, 1);
    gemm_mma<0><<<gG, 256, GEMM_SMEM>>>(yf, wt + 3 * WT_SZ, bp, bp, bp, out, nullptr);
}